// round 6
// baseline (speedup 1.0000x reference)
#include <cuda_runtime.h>
#include <cuda_bf16.h>
#include <cstdint>

// ---------------- problem constants ----------------
#define CIN 128
#define COUT 256
#define NPIX (8 * 128 * 128)               // input pixels
#define M_TOTAL 32768                      // 8 * 64 * 64
#define K_TOTAL 1152                       // 9 * 128
#define FEATS_OUT_ELEMS ((size_t)M_TOTAL * COUT)
#define COORD_OUT_ELEMS ((size_t)M_TOTAL * 3)

// ---------------- GEMM config ----------------
#define BM 128
#define BN 128
#define BK 32                 // bf16 k per chunk
#define NCHUNK 36             // K_TOTAL / BK
#define NSTAGE 3
#define NTHREADS 256

// smem stage: A [128 rows][128B] then B [128 rows][128B]
// row = [32k hi (64B) | 32k lo (64B)], SW128 chunk swizzle: phys16B = c ^ (row&7)
#define OFF_B 16384
#define STAGE_BYTES 32768
#define SMEM_TOTAL (NSTAGE * STAGE_BYTES)   // 98304; 2 CTAs/SM -> 192KB/SM

// ---------------- device scratch ----------------
__device__ __align__(16) __nv_bfloat16 g_Whi[COUT * K_TOTAL];
__device__ __align__(16) __nv_bfloat16 g_Wlo[COUT * K_TOTAL];
__device__ __align__(16) __nv_bfloat16 g_Ahi[(size_t)NPIX * CIN];
__device__ __align__(16) __nv_bfloat16 g_Alo[(size_t)NPIX * CIN];

// ---------------- helpers ----------------
__device__ __forceinline__ uint32_t smem_u32(const void* p) {
    uint32_t a;
    asm("{ .reg .u64 t; cvta.to.shared.u64 t, %1; cvt.u32.u64 %0, t; }" : "=r"(a) : "l"(p));
    return a;
}
__device__ __forceinline__ void cp_async16(uint32_t dst, const void* src) {
    asm volatile("cp.async.cg.shared.global [%0], [%1], 16;" :: "r"(dst), "l"(src) : "memory");
}
__device__ __forceinline__ void cp_async16z(uint32_t dst, const void* src, uint32_t src_size) {
    asm volatile("cp.async.cg.shared.global [%0], [%1], 16, %2;"
                 :: "r"(dst), "l"(src), "r"(src_size) : "memory");
}
__device__ __forceinline__ void cp_commit() {
    asm volatile("cp.async.commit_group;" ::: "memory");
}
template <int N>
__device__ __forceinline__ void cp_wait() {
    asm volatile("cp.async.wait_group %0;" :: "n"(N) : "memory");
}
__device__ __forceinline__ void ldsm_x4(uint32_t& r0, uint32_t& r1, uint32_t& r2, uint32_t& r3,
                                        uint32_t addr) {
    asm volatile("ldmatrix.sync.aligned.m8n8.x4.shared.b16 {%0,%1,%2,%3}, [%4];"
                 : "=r"(r0), "=r"(r1), "=r"(r2), "=r"(r3) : "r"(addr));
}
__device__ __forceinline__ void mma16816(float* c, const uint32_t* a, uint32_t b0, uint32_t b1) {
    asm volatile("mma.sync.aligned.m16n8k16.row.col.f32.bf16.bf16.f32 "
                 "{%0,%1,%2,%3}, {%4,%5,%6,%7}, {%8,%9}, {%0,%1,%2,%3};"
                 : "+f"(c[0]), "+f"(c[1]), "+f"(c[2]), "+f"(c[3])
                 : "r"(a[0]), "r"(a[1]), "r"(a[2]), "r"(a[3]), "r"(b0), "r"(b1));
}

// ---------------- weight split + transpose (coalesced, tiled) ----------------
// weight[k][n] fp32 -> g_Whi/g_Wlo [n][k] bf16
__global__ __launch_bounds__(256)
void wconv_kernel(const float* __restrict__ w) {
    __shared__ float tile[32][33];
    const int kt = blockIdx.x;              // 36 tiles of 32 k
    const int nt = blockIdx.y;              // 8 tiles of 32 n
    const int ty = threadIdx.x >> 5;        // 0..7
    const int tx = threadIdx.x & 31;
    #pragma unroll
    for (int j = 0; j < 4; ++j) {
        const int kr = kt * 32 + ty + j * 8;
        tile[ty + j * 8][tx] = w[(size_t)kr * COUT + nt * 32 + tx];
    }
    __syncthreads();
    #pragma unroll
    for (int j = 0; j < 4; ++j) {
        const int nr = nt * 32 + ty + j * 8;
        const int k  = kt * 32 + tx;
        const float x = tile[tx][ty + j * 8];
        __nv_bfloat16 h = __float2bfloat16(x);
        g_Whi[(size_t)nr * K_TOTAL + k] = h;
        g_Wlo[(size_t)nr * K_TOTAL + k] = __float2bfloat16(x - __bfloat162float(h));
    }
}

// ---------------- feats split (streaming) ----------------
__global__ __launch_bounds__(256)
void asplit_kernel(const float* __restrict__ feats) {
    size_t i4 = (size_t)blockIdx.x * 256 + threadIdx.x;
    const size_t total4 = (size_t)NPIX * CIN / 4;
    if (i4 < total4) {
        float4 v = reinterpret_cast<const float4*>(feats)[i4];
        __nv_bfloat162 h0 = __floats2bfloat162_rn(v.x, v.y);
        __nv_bfloat162 h1 = __floats2bfloat162_rn(v.z, v.w);
        __nv_bfloat162 l0 = __floats2bfloat162_rn(v.x - __bfloat162float(h0.x),
                                                  v.y - __bfloat162float(h0.y));
        __nv_bfloat162 l1 = __floats2bfloat162_rn(v.z - __bfloat162float(h1.x),
                                                  v.w - __bfloat162float(h1.y));
        reinterpret_cast<uint2*>(g_Ahi)[i4] =
            make_uint2(*reinterpret_cast<uint32_t*>(&h0), *reinterpret_cast<uint32_t*>(&h1));
        reinterpret_cast<uint2*>(g_Alo)[i4] =
            make_uint2(*reinterpret_cast<uint32_t*>(&l0), *reinterpret_cast<uint32_t*>(&l1));
    }
}

// ---------------- main GEMM kernel ----------------
__global__ __launch_bounds__(NTHREADS, 2)
void conv_mma_kernel(const float* __restrict__ alpha,
                     float* __restrict__ out)
{
    extern __shared__ char smem[];
    const uint32_t sb = smem_u32(smem);
    const int tid = threadIdx.x;
    const int w = tid >> 5, l = tid & 31;
    const int mblk = blockIdx.x, nblk = blockIdx.y;
    const int wm = w & 3, wn = w >> 2;      // 4 m-warps x 2 n-warps, warp tile 32x64

    if (nblk == 0) {
        if (tid < 128) {
            int p = mblk * 128 + tid;
            float* row = out + FEATS_OUT_ELEMS + (size_t)p * 3;
            row[0] = (float)(p >> 12);
            row[1] = (float)((p & 4095) >> 6);
            row[2] = (float)(p & 63);
        }
        if (mblk == 0 && tid == 128)
            out[FEATS_OUT_ELEMS + COORD_OUT_ELEMS] = alpha[0];
    }

    // ---- loader geometry: thread t -> row (0..127), half h (0=hi,1=lo)
    const int lrow = tid >> 1;
    const int lh   = tid & 1;
    // A side
    const int p   = mblk * 128 + lrow;
    const int ab  = p >> 12;
    const int aoy = ((p & 4095) >> 6) << 1;
    const int aox = (p & 63) << 1;
    // B side
    const int bgn = nblk * 128 + lrow;

    // physical 16B chunk offsets for this thread's 4 cp.asyncs (logical chunks 4h..4h+3)
    uint32_t adst_c[4], bdst_c[4];
    {
        const int rs = lrow & 7;
        #pragma unroll
        for (int j = 0; j < 4; ++j) {
            adst_c[j] = (uint32_t)(((4 * lh + j) ^ rs) * 16);
            bdst_c[j] = adst_c[j];
        }
    }

    auto issue_chunk = [&](int cc, int stg) {
        const int tap = cc >> 2, kc = (cc & 3) << 5;
        // A
        const int iy = aoy + tap / 3 - 1;
        const int ix = aox + tap % 3 - 1;
        const bool valid = ((unsigned)iy < 128u) && ((unsigned)ix < 128u);
        const uint32_t vs = valid ? 16u : 0u;
        const int cy = valid ? iy : 0, cx = valid ? ix : 0;
        const __nv_bfloat16* asrc =
            (lh ? g_Alo : g_Ahi) + ((size_t)(((ab << 7) + cy) << 7) + cx) * CIN + kc;
        const uint32_t arow_base = sb + (uint32_t)stg * STAGE_BYTES + lrow * 128;
        #pragma unroll
        for (int j = 0; j < 4; ++j)
            cp_async16z(arow_base + adst_c[j], asrc + j * 8, vs);
        // B
        const __nv_bfloat16* bsrc =
            (lh ? g_Wlo : g_Whi) + (size_t)bgn * K_TOTAL + (size_t)tap * 128 + kc;
        const uint32_t brow_base = sb + (uint32_t)stg * STAGE_BYTES + OFF_B + lrow * 128;
        #pragma unroll
        for (int j = 0; j < 4; ++j)
            cp_async16(brow_base + bdst_c[j], bsrc + j * 8);
    };

    float acc[2][8][4];
    #pragma unroll
    for (int i = 0; i < 2; ++i)
        #pragma unroll
        for (int j = 0; j < 8; ++j)
            #pragma unroll
            for (int q = 0; q < 4; ++q) acc[i][j][q] = 0.f;

    // ---- precompute ldsm addresses (stage-0 base; add stage offset in loop)
    // A: arow = wm*32 + mt*16 + (l&15), chunk c = (kb + (l>>4)*8)/8 in 0..3
    uint32_t a_addr[2][2];   // [k16][mt]
    uint32_t b_addr[2][4];   // [k16][np]
    #pragma unroll
    for (int k16 = 0; k16 < 2; ++k16) {
        #pragma unroll
        for (int mt = 0; mt < 2; ++mt) {
            const int arow = wm * 32 + mt * 16 + (l & 15);
            const int c = k16 * 2 + (l >> 4);
            a_addr[k16][mt] = sb + arow * 128 + ((c ^ (arow & 7)) * 16);
        }
        #pragma unroll
        for (int np = 0; np < 4; ++np) {
            const int brow = wn * 64 + np * 16 + ((l >> 4) << 3) + (l & 7);
            const int c = k16 * 2 + ((l >> 3) & 1);
            b_addr[k16][np] = sb + OFF_B + brow * 128 + ((c ^ (brow & 7)) * 16);
        }
    }

    // ---- prologue: fill 2 stages
    issue_chunk(0, 0); cp_commit();
    issue_chunk(1, 1); cp_commit();

    #pragma unroll 1
    for (int c = 0; c < NCHUNK; ++c) {
        const uint32_t soff = (uint32_t)(c % NSTAGE) * STAGE_BYTES;

        cp_wait<1>();
        __syncthreads();

        if (c + 2 < NCHUNK) {
            issue_chunk(c + 2, (c + 2) % NSTAGE);
            cp_commit();
        }

        #pragma unroll
        for (int k16 = 0; k16 < 2; ++k16) {
            uint32_t ahi[2][4], alo[2][4];
            #pragma unroll
            for (int mt = 0; mt < 2; ++mt) {
                const uint32_t aa = a_addr[k16][mt] + soff;
                ldsm_x4(ahi[mt][0], ahi[mt][1], ahi[mt][2], ahi[mt][3], aa);
                ldsm_x4(alo[mt][0], alo[mt][1], alo[mt][2], alo[mt][3], aa ^ 64);
            }
            #pragma unroll
            for (int np = 0; np < 4; ++np) {
                const uint32_t ba = b_addr[k16][np] + soff;
                uint32_t bh[4], bl[4];
                ldsm_x4(bh[0], bh[1], bh[2], bh[3], ba);
                ldsm_x4(bl[0], bl[1], bl[2], bl[3], ba ^ 64);
                #pragma unroll
                for (int mt = 0; mt < 2; ++mt) {
                    #pragma unroll
                    for (int sub = 0; sub < 2; ++sub) {
                        float* a4 = acc[mt][np * 2 + sub];
                        mma16816(a4, ahi[mt], bh[sub * 2], bh[sub * 2 + 1]);
                        mma16816(a4, ahi[mt], bl[sub * 2], bl[sub * 2 + 1]);
                        mma16816(a4, alo[mt], bh[sub * 2], bh[sub * 2 + 1]);
                    }
                }
            }
        }

        // barrier before anyone refills the stage consumed 2 iterations from now
        __syncthreads();
    }

    // ---- epilogue ----
    const int row_base = mblk * 128 + wm * 32 + (l >> 2);
    const int col_base = nblk * 128 + wn * 64 + (l & 3) * 2;
    #pragma unroll
    for (int mt = 0; mt < 2; ++mt) {
        #pragma unroll
        for (int nt = 0; nt < 8; ++nt) {
            const int r0 = row_base + mt * 16;
            const int cc = col_base + nt * 8;
            float* o0 = out + (size_t)r0 * COUT + cc;
            float* o1 = out + (size_t)(r0 + 8) * COUT + cc;
            *reinterpret_cast<float2*>(o0) = make_float2(acc[mt][nt][0], acc[mt][nt][1]);
            *reinterpret_cast<float2*>(o1) = make_float2(acc[mt][nt][2], acc[mt][nt][3]);
        }
    }
}

// ---------------- launch ----------------
extern "C" void kernel_launch(void* const* d_in, const int* in_sizes, int n_in,
                              void* d_out, int out_size)
{
    const float* feats  = (const float*)d_in[0];
    const float* weight = (const float*)d_in[1];
    const float* alpha  = (const float*)d_in[2];
    float* out = (float*)d_out;

    cudaFuncSetAttribute(conv_mma_kernel,
                         cudaFuncAttributeMaxDynamicSharedMemorySize, SMEM_TOTAL);

    dim3 wgrid(K_TOTAL / 32, COUT / 32);   // (36, 8)
    wconv_kernel<<<wgrid, 256>>>(weight);
    asplit_kernel<<<(NPIX * CIN / 4 + 255) / 256, 256>>>(feats);
    dim3 grid(M_TOTAL / BM, COUT / BN);    // (256, 2)
    conv_mma_kernel<<<grid, NTHREADS, SMEM_TOTAL>>>(alpha, out);
}

// round 7
// speedup vs baseline: 1.0793x; 1.0793x over previous
#include <cuda_runtime.h>
#include <cuda_bf16.h>
#include <cstdint>

// ---------------- problem constants ----------------
#define CIN 128
#define COUT 256
#define NPIX (8 * 128 * 128)
#define M_TOTAL 32768                      // 8 * 64 * 64
#define K_TOTAL 1152                       // 9 * 128
#define FEATS_OUT_ELEMS ((size_t)M_TOTAL * COUT)
#define COORD_OUT_ELEMS ((size_t)M_TOTAL * 3)

// ---------------- GEMM config ----------------
#define BM 256
#define BN 128
#define BK 32                 // bf16 k per chunk
#define NCHUNK 36             // K_TOTAL / BK
#define NSTAGE 3
#define NTHREADS 256          // 8 warps: 4 m-warps x 2 n-warps, warp tile 64x64

// smem stage: A [256 rows][128B] then B [128 rows][128B]
// row = [32k hi (64B) | 32k lo (64B)], swizzle: phys16B = chunk ^ (row&7)
#define OFF_B 32768
#define STAGE_BYTES 49152
#define SMEM_TOTAL (NSTAGE * STAGE_BYTES)   // 147456, 1 CTA/SM

// ---------------- device scratch ----------------
__device__ __align__(16) __nv_bfloat16 g_Whi[COUT * K_TOTAL];
__device__ __align__(16) __nv_bfloat16 g_Wlo[COUT * K_TOTAL];
__device__ __align__(16) __nv_bfloat16 g_Ahi[(size_t)NPIX * CIN];
__device__ __align__(16) __nv_bfloat16 g_Alo[(size_t)NPIX * CIN];

// ---------------- helpers ----------------
__device__ __forceinline__ uint32_t smem_u32(const void* p) {
    uint32_t a;
    asm("{ .reg .u64 t; cvta.to.shared.u64 t, %1; cvt.u32.u64 %0, t; }" : "=r"(a) : "l"(p));
    return a;
}
__device__ __forceinline__ void cp_async16(uint32_t dst, const void* src) {
    asm volatile("cp.async.cg.shared.global [%0], [%1], 16;" :: "r"(dst), "l"(src) : "memory");
}
__device__ __forceinline__ void cp_async16z(uint32_t dst, const void* src, uint32_t src_size) {
    asm volatile("cp.async.cg.shared.global [%0], [%1], 16, %2;"
                 :: "r"(dst), "l"(src), "r"(src_size) : "memory");
}
__device__ __forceinline__ void cp_commit() {
    asm volatile("cp.async.commit_group;" ::: "memory");
}
template <int N>
__device__ __forceinline__ void cp_wait() {
    asm volatile("cp.async.wait_group %0;" :: "n"(N) : "memory");
}
__device__ __forceinline__ void ldsm_x4(uint32_t& r0, uint32_t& r1, uint32_t& r2, uint32_t& r3,
                                        uint32_t addr) {
    asm volatile("ldmatrix.sync.aligned.m8n8.x4.shared.b16 {%0,%1,%2,%3}, [%4];"
                 : "=r"(r0), "=r"(r1), "=r"(r2), "=r"(r3) : "r"(addr));
}
__device__ __forceinline__ void mma16816(float* c, const uint32_t* a, uint32_t b0, uint32_t b1) {
    asm volatile("mma.sync.aligned.m16n8k16.row.col.f32.bf16.bf16.f32 "
                 "{%0,%1,%2,%3}, {%4,%5,%6,%7}, {%8,%9}, {%0,%1,%2,%3};"
                 : "+f"(c[0]), "+f"(c[1]), "+f"(c[2]), "+f"(c[3])
                 : "r"(a[0]), "r"(a[1]), "r"(a[2]), "r"(a[3]), "r"(b0), "r"(b1));
}

// ---------------- weight split + transpose (coalesced, tiled) ----------------
__global__ __launch_bounds__(256)
void wconv_kernel(const float* __restrict__ w) {
    __shared__ float tile[32][33];
    const int kt = blockIdx.x, nt = blockIdx.y;
    const int ty = threadIdx.x >> 5, tx = threadIdx.x & 31;
    #pragma unroll
    for (int j = 0; j < 4; ++j)
        tile[ty + j * 8][tx] = w[(size_t)(kt * 32 + ty + j * 8) * COUT + nt * 32 + tx];
    __syncthreads();
    #pragma unroll
    for (int j = 0; j < 4; ++j) {
        const int nr = nt * 32 + ty + j * 8;
        const int k  = kt * 32 + tx;
        const float x = tile[tx][ty + j * 8];
        __nv_bfloat16 h = __float2bfloat16(x);
        g_Whi[(size_t)nr * K_TOTAL + k] = h;
        g_Wlo[(size_t)nr * K_TOTAL + k] = __float2bfloat16(x - __bfloat162float(h));
    }
}

// ---------------- feats split (streaming, bandwidth-bound) ----------------
__global__ __launch_bounds__(256)
void asplit_kernel(const float* __restrict__ feats) {
    size_t i4 = (size_t)blockIdx.x * 256 + threadIdx.x;
    if (i4 < (size_t)NPIX * CIN / 4) {
        float4 v = reinterpret_cast<const float4*>(feats)[i4];
        __nv_bfloat162 h0 = __floats2bfloat162_rn(v.x, v.y);
        __nv_bfloat162 h1 = __floats2bfloat162_rn(v.z, v.w);
        __nv_bfloat162 l0 = __floats2bfloat162_rn(v.x - __bfloat162float(h0.x),
                                                  v.y - __bfloat162float(h0.y));
        __nv_bfloat162 l1 = __floats2bfloat162_rn(v.z - __bfloat162float(h1.x),
                                                  v.w - __bfloat162float(h1.y));
        reinterpret_cast<uint2*>(g_Ahi)[i4] =
            make_uint2(*reinterpret_cast<uint32_t*>(&h0), *reinterpret_cast<uint32_t*>(&h1));
        reinterpret_cast<uint2*>(g_Alo)[i4] =
            make_uint2(*reinterpret_cast<uint32_t*>(&l0), *reinterpret_cast<uint32_t*>(&l1));
    }
}

// ---------------- main GEMM kernel ----------------
__global__ __launch_bounds__(NTHREADS, 1)
void conv_mma_kernel(const float* __restrict__ alpha,
                     float* __restrict__ out)
{
    extern __shared__ char smem[];
    const uint32_t sb = smem_u32(smem);
    const int tid = threadIdx.x;
    const int w = tid >> 5, l = tid & 31;
    const int mblk = blockIdx.x, nblk = blockIdx.y;
    const int wm = w & 3, wn = w >> 2;      // warp tile 64x64

    if (nblk == 0) {
        int p = mblk * 256 + tid;
        float* row = out + FEATS_OUT_ELEMS + (size_t)p * 3;
        row[0] = (float)(p >> 12);
        row[1] = (float)((p & 4095) >> 6);
        row[2] = (float)(p & 63);
        if (mblk == 0 && tid == 0)
            out[FEATS_OUT_ELEMS + COORD_OUT_ELEMS] = alpha[0];
    }

    // ---- loader geometry ----
    // A: 512 row-half tasks; thread handles rows (tid>>1) and (tid>>1)+128, half = tid&1
    const int lh    = tid & 1;
    const int arow0 = tid >> 1;
    // pixel decode for both A rows
    int ab[2], aoy[2], aox[2];
    #pragma unroll
    for (int r = 0; r < 2; ++r) {
        const int p = mblk * 256 + arow0 + r * 128;
        ab[r]  = p >> 12;
        aoy[r] = ((p & 4095) >> 6) << 1;
        aox[r] = (p & 63) << 1;
    }
    // B: 256 row-half tasks; thread handles row tid>>1, half = tid&1
    const int brow = tid >> 1;
    const int bgn  = nblk * 128 + brow;

    auto issue_chunk = [&](int cc, int stg) {
        const int tap = cc >> 2, kc = (cc & 3) << 5;
        const int dy = tap / 3 - 1, dx = tap % 3 - 1;
        const uint32_t stage = sb + (uint32_t)stg * STAGE_BYTES;
        const __nv_bfloat16* aplane = lh ? g_Alo : g_Ahi;
        #pragma unroll
        for (int r = 0; r < 2; ++r) {
            const int arow = arow0 + r * 128;
            const int iy = aoy[r] + dy, ix = aox[r] + dx;
            const bool valid = ((unsigned)iy < 128u) && ((unsigned)ix < 128u);
            const uint32_t vs = valid ? 16u : 0u;
            const int cy = valid ? iy : 0, cx = valid ? ix : 0;
            const __nv_bfloat16* asrc =
                aplane + ((size_t)(((ab[r] << 7) + cy) << 7) + cx) * CIN + kc;
            const uint32_t arb = stage + arow * 128;
            const int rs = arow & 7;
            #pragma unroll
            for (int j = 0; j < 4; ++j)
                cp_async16z(arb + (((4 * lh + j) ^ rs) * 16), asrc + j * 8, vs);
        }
        const __nv_bfloat16* bsrc =
            (lh ? g_Wlo : g_Whi) + (size_t)bgn * K_TOTAL + (size_t)tap * 128 + kc;
        const uint32_t brb = stage + OFF_B + brow * 128;
        const int rsb = brow & 7;
        #pragma unroll
        for (int j = 0; j < 4; ++j)
            cp_async16(brb + (((4 * lh + j) ^ rsb) * 16), bsrc + j * 8);
    };

    float acc[4][8][4];
    #pragma unroll
    for (int i = 0; i < 4; ++i)
        #pragma unroll
        for (int j = 0; j < 8; ++j)
            #pragma unroll
            for (int q = 0; q < 4; ++q) acc[i][j][q] = 0.f;

    // ---- ldsm address components (small, shared swizzle residue l&7) ----
    const int rs_l = l & 7;
    uint32_t a_rowbase[4], b_rowbase[4];
    #pragma unroll
    for (int mt = 0; mt < 4; ++mt)
        a_rowbase[mt] = sb + (wm * 64 + mt * 16 + (l & 15)) * 128;
    #pragma unroll
    for (int nb = 0; nb < 4; ++nb)
        b_rowbase[nb] = sb + OFF_B + (wn * 64 + nb * 16 + ((l >> 4) << 3) + (l & 7)) * 128;
    uint32_t a_off[2], b_off[2];
    #pragma unroll
    for (int k16 = 0; k16 < 2; ++k16) {
        a_off[k16] = (uint32_t)(((k16 * 2 + (l >> 4)) ^ rs_l) * 16);
        b_off[k16] = (uint32_t)(((k16 * 2 + ((l >> 3) & 1)) ^ rs_l) * 16);
    }

    // ---- prologue: fill 2 stages ----
    issue_chunk(0, 0); cp_commit();
    issue_chunk(1, 1); cp_commit();

    #pragma unroll 1
    for (int c = 0; c < NCHUNK; ++c) {
        const uint32_t soff = (uint32_t)(c % NSTAGE) * STAGE_BYTES;

        cp_wait<1>();
        __syncthreads();            // all warps done with stage (c-1)%NSTAGE

        if (c + 2 < NCHUNK) {
            issue_chunk(c + 2, (c + 2) % NSTAGE);
            cp_commit();
        }

        #pragma unroll
        for (int k16 = 0; k16 < 2; ++k16) {
            uint32_t ahi[4][4], alo[4][4];
            #pragma unroll
            for (int mt = 0; mt < 4; ++mt) {
                const uint32_t aa = a_rowbase[mt] + a_off[k16] + soff;
                ldsm_x4(ahi[mt][0], ahi[mt][1], ahi[mt][2], ahi[mt][3], aa);
                ldsm_x4(alo[mt][0], alo[mt][1], alo[mt][2], alo[mt][3], aa ^ 64);
            }
            #pragma unroll
            for (int nb = 0; nb < 4; ++nb) {
                const uint32_t ba = b_rowbase[nb] + b_off[k16] + soff;
                uint32_t bh[4], bl[4];
                ldsm_x4(bh[0], bh[1], bh[2], bh[3], ba);
                ldsm_x4(bl[0], bl[1], bl[2], bl[3], ba ^ 64);
                #pragma unroll
                for (int mt = 0; mt < 4; ++mt) {
                    #pragma unroll
                    for (int sub = 0; sub < 2; ++sub) {
                        float* a4 = acc[mt][nb * 2 + sub];
                        mma16816(a4, ahi[mt], bh[sub * 2], bh[sub * 2 + 1]);
                        mma16816(a4, ahi[mt], bl[sub * 2], bl[sub * 2 + 1]);
                        mma16816(a4, alo[mt], bh[sub * 2], bh[sub * 2 + 1]);
                    }
                }
            }
        }
    }

    // ---- epilogue ----
    const int row_base = mblk * 256 + wm * 64 + (l >> 2);
    const int col_base = nblk * 128 + wn * 64 + (l & 3) * 2;
    #pragma unroll
    for (int mt = 0; mt < 4; ++mt) {
        #pragma unroll
        for (int nt = 0; nt < 8; ++nt) {
            const int r0 = row_base + mt * 16;
            const int cc = col_base + nt * 8;
            float* o0 = out + (size_t)r0 * COUT + cc;
            float* o1 = out + (size_t)(r0 + 8) * COUT + cc;
            *reinterpret_cast<float2*>(o0) = make_float2(acc[mt][nt][0], acc[mt][nt][1]);
            *reinterpret_cast<float2*>(o1) = make_float2(acc[mt][nt][2], acc[mt][nt][3]);
        }
    }
}

// ---------------- launch ----------------
extern "C" void kernel_launch(void* const* d_in, const int* in_sizes, int n_in,
                              void* d_out, int out_size)
{
    const float* feats  = (const float*)d_in[0];
    const float* weight = (const float*)d_in[1];
    const float* alpha  = (const float*)d_in[2];
    float* out = (float*)d_out;

    cudaFuncSetAttribute(conv_mma_kernel,
                         cudaFuncAttributeMaxDynamicSharedMemorySize, SMEM_TOTAL);

    dim3 wgrid(K_TOTAL / 32, COUT / 32);   // (36, 8)
    wconv_kernel<<<wgrid, 256>>>(weight);
    asplit_kernel<<<(NPIX * CIN / 4 + 255) / 256, 256>>>(feats);
    dim3 grid(M_TOTAL / BM, COUT / BN);    // (128, 2)
    conv_mma_kernel<<<grid, NTHREADS, SMEM_TOTAL>>>(alpha, out);
}

// round 8
// speedup vs baseline: 1.8377x; 1.7026x over previous
#include <cuda_runtime.h>
#include <cuda_fp16.h>
#include <cstdint>

// ---------------- problem constants ----------------
#define CIN 128
#define COUT 256
#define NPIX (8 * 128 * 128)
#define M_TOTAL 32768                      // 8 * 64 * 64
#define K_TOTAL 1152                       // 9 * 128
#define FEATS_OUT_ELEMS ((size_t)M_TOTAL * COUT)
#define COORD_OUT_ELEMS ((size_t)M_TOTAL * 3)

// ---------------- GEMM config ----------------
#define BM 128
#define BN 128
#define BK 32                 // k per chunk
#define NCHUNK 36
#define NSTAGE 3
#define NTHREADS 256          // 8 warps: 4 m x 2 n, warp tile 32x64

// smem stage:
//   A: 128 rows x 128B;  row = [hi k0..31 (chunks 0-3) | lo k0..31 (chunks 4-7)]
//      phys16B(chunk) = (chunk ^ (row & 7)) * 16            (conflict-free)
//   B: 128 rows x 64B (hi only); phys16B = (chunk ^ ((row>>1) & 3)) * 16
#define OFF_B 16384
#define STAGE_BYTES 24576
#define SMEM_TOTAL (NSTAGE * STAGE_BYTES)   // 73728; 2 CTAs/SM -> 147KB/SM

// ---------------- device scratch ----------------
__device__ __align__(16) __half g_Wh [COUT * K_TOTAL];           // [n][k] fp16
__device__ __align__(16) __half g_Ahi[(size_t)NPIX * CIN];
__device__ __align__(16) __half g_Alo[(size_t)NPIX * CIN];

// ---------------- helpers ----------------
__device__ __forceinline__ uint32_t smem_u32(const void* p) {
    uint32_t a;
    asm("{ .reg .u64 t; cvta.to.shared.u64 t, %1; cvt.u32.u64 %0, t; }" : "=r"(a) : "l"(p));
    return a;
}
__device__ __forceinline__ void cp_async16(uint32_t dst, const void* src) {
    asm volatile("cp.async.cg.shared.global [%0], [%1], 16;" :: "r"(dst), "l"(src) : "memory");
}
__device__ __forceinline__ void cp_async16z(uint32_t dst, const void* src, uint32_t src_size) {
    asm volatile("cp.async.cg.shared.global [%0], [%1], 16, %2;"
                 :: "r"(dst), "l"(src), "r"(src_size) : "memory");
}
__device__ __forceinline__ void cp_commit() {
    asm volatile("cp.async.commit_group;" ::: "memory");
}
template <int N>
__device__ __forceinline__ void cp_wait() {
    asm volatile("cp.async.wait_group %0;" :: "n"(N) : "memory");
}
__device__ __forceinline__ void ldsm_x4(uint32_t& r0, uint32_t& r1, uint32_t& r2, uint32_t& r3,
                                        uint32_t addr) {
    asm volatile("ldmatrix.sync.aligned.m8n8.x4.shared.b16 {%0,%1,%2,%3}, [%4];"
                 : "=r"(r0), "=r"(r1), "=r"(r2), "=r"(r3) : "r"(addr));
}
__device__ __forceinline__ void mma16816(float* c, const uint32_t* a, uint32_t b0, uint32_t b1) {
    asm volatile("mma.sync.aligned.m16n8k16.row.col.f32.f16.f16.f32 "
                 "{%0,%1,%2,%3}, {%4,%5,%6,%7}, {%8,%9}, {%0,%1,%2,%3};"
                 : "+f"(c[0]), "+f"(c[1]), "+f"(c[2]), "+f"(c[3])
                 : "r"(a[0]), "r"(a[1]), "r"(a[2]), "r"(a[3]), "r"(b0), "r"(b1));
}

// ---------------- weight round + transpose (coalesced, tiled) ----------------
// weight[k][n] fp32 -> g_Wh [n][k] fp16
__global__ __launch_bounds__(256)
void wconv_kernel(const float* __restrict__ w) {
    __shared__ float tile[32][33];
    const int kt = blockIdx.x, nt = blockIdx.y;
    const int ty = threadIdx.x >> 5, tx = threadIdx.x & 31;
    #pragma unroll
    for (int j = 0; j < 4; ++j)
        tile[ty + j * 8][tx] = w[(size_t)(kt * 32 + ty + j * 8) * COUT + nt * 32 + tx];
    __syncthreads();
    #pragma unroll
    for (int j = 0; j < 4; ++j) {
        const int nr = nt * 32 + ty + j * 8;
        const int k  = kt * 32 + tx;
        g_Wh[(size_t)nr * K_TOTAL + k] = __float2half_rn(tile[tx][ty + j * 8]);
    }
}

// ---------------- feats split fp32 -> fp16 hi + lo (streaming) ----------------
__global__ __launch_bounds__(256)
void asplit_kernel(const float* __restrict__ feats) {
    size_t i4 = (size_t)blockIdx.x * 256 + threadIdx.x;
    if (i4 < (size_t)NPIX * CIN / 4) {
        float4 v = reinterpret_cast<const float4*>(feats)[i4];
        __half2 h0 = __floats2half2_rn(v.x, v.y);
        __half2 h1 = __floats2half2_rn(v.z, v.w);
        __half2 l0 = __floats2half2_rn(v.x - __half2float(h0.x),
                                       v.y - __half2float(h0.y));
        __half2 l1 = __floats2half2_rn(v.z - __half2float(h1.x),
                                       v.w - __half2float(h1.y));
        reinterpret_cast<uint2*>(g_Ahi)[i4] =
            make_uint2(*reinterpret_cast<uint32_t*>(&h0), *reinterpret_cast<uint32_t*>(&h1));
        reinterpret_cast<uint2*>(g_Alo)[i4] =
            make_uint2(*reinterpret_cast<uint32_t*>(&l0), *reinterpret_cast<uint32_t*>(&l1));
    }
}

// ---------------- main GEMM kernel ----------------
__global__ __launch_bounds__(NTHREADS, 2)
void conv_mma_kernel(const float* __restrict__ alpha,
                     float* __restrict__ out)
{
    extern __shared__ char smem[];
    const uint32_t sb = smem_u32(smem);
    const int tid = threadIdx.x;
    const int w = tid >> 5, l = tid & 31;
    const int mblk = blockIdx.x, nblk = blockIdx.y;
    const int wm = w & 3, wn = w >> 2;      // warp tile 32x64

    if (nblk == 0) {
        if (tid < 128) {
            int p = mblk * 128 + tid;
            float* row = out + FEATS_OUT_ELEMS + (size_t)p * 3;
            row[0] = (float)(p >> 12);
            row[1] = (float)((p & 4095) >> 6);
            row[2] = (float)(p & 63);
        }
        if (mblk == 0 && tid == 128)
            out[FEATS_OUT_ELEMS + COORD_OUT_ELEMS] = alpha[0];
    }

    // ---- loader geometry: thread t -> row t>>1, k-half h = t&1 (k = 16h..16h+15)
    const int lrow = tid >> 1;
    const int lh   = tid & 1;
    const int p    = mblk * 128 + lrow;
    const int ab   = p >> 12;
    const int aoy  = ((p & 4095) >> 6) << 1;
    const int aox  = (p & 63) << 1;
    const int bgn  = nblk * 128 + lrow;

    // precomputed physical chunk offsets (16B units pre-multiplied)
    const int ars = lrow & 7;
    const int brs = (lrow >> 1) & 3;
    uint32_t a_hi0 = ((2 * lh)     ^ ars) * 16u, a_hi1 = ((2 * lh + 1) ^ ars) * 16u;
    uint32_t a_lo0 = ((2 * lh + 4) ^ ars) * 16u, a_lo1 = ((2 * lh + 5) ^ ars) * 16u;
    uint32_t b_c0  = ((2 * lh)     ^ brs) * 16u, b_c1  = ((2 * lh + 1) ^ brs) * 16u;

    auto issue_chunk = [&](int cc, int stg) {
        const int tap = cc >> 2, kc = (cc & 3) << 5;
        const int iy = aoy + tap / 3 - 1;
        const int ix = aox + tap % 3 - 1;
        const bool valid = ((unsigned)iy < 128u) && ((unsigned)ix < 128u);
        const uint32_t vs = valid ? 16u : 0u;
        const int cy = valid ? iy : 0, cx = valid ? ix : 0;
        const size_t apix = ((size_t)(((ab << 7) + cy) << 7) + cx) * CIN + kc + lh * 16;
        const uint32_t stage = sb + (uint32_t)stg * STAGE_BYTES;
        const uint32_t arb = stage + lrow * 128;
        cp_async16z(arb + a_hi0, g_Ahi + apix,     vs);
        cp_async16z(arb + a_hi1, g_Ahi + apix + 8, vs);
        cp_async16z(arb + a_lo0, g_Alo + apix,     vs);
        cp_async16z(arb + a_lo1, g_Alo + apix + 8, vs);
        const __half* bsrc = g_Wh + (size_t)bgn * K_TOTAL + (size_t)tap * 128 + kc + lh * 16;
        const uint32_t brb = stage + OFF_B + lrow * 64;
        cp_async16(brb + b_c0, bsrc);
        cp_async16(brb + b_c1, bsrc + 8);
    };

    float acc[2][8][4];
    #pragma unroll
    for (int i = 0; i < 2; ++i)
        #pragma unroll
        for (int j = 0; j < 8; ++j)
            #pragma unroll
            for (int q = 0; q < 4; ++q) acc[i][j][q] = 0.f;

    // ---- ldsm addressing ----
    // A: arow = wm*32 + mt*16 + (l&15); hi chunk = k16*2 + (l>>4); lo = hi^64
    const int arow_l = wm * 32 + (l & 15);
    const int a_rs   = arow_l & 7;                 // invariant in mt (mt*16)
    const uint32_t a_base0 = sb + arow_l * 128;
    // B: brow = wn*64 + np*16 + ((l>>4)<<3) + (l&7); chunk = k16*2 + ((l>>3)&1)
    const int brow_l = wn * 64 + ((l >> 4) << 3) + (l & 7);
    const int b_rs   = (brow_l >> 1) & 3;          // invariant in np (np*16)
    const uint32_t b_base0 = sb + OFF_B + brow_l * 64;

    // ---- prologue: fill 2 stages ----
    issue_chunk(0, 0); cp_commit();
    issue_chunk(1, 1); cp_commit();

    #pragma unroll 1
    for (int c = 0; c < NCHUNK; ++c) {
        const uint32_t soff = (uint32_t)(c % NSTAGE) * STAGE_BYTES;

        cp_wait<1>();
        __syncthreads();           // all warps finished stage (c-1)%NSTAGE

        if (c + 2 < NCHUNK) issue_chunk(c + 2, (c + 2) % NSTAGE);
        cp_commit();               // unconditional: keeps group indices advancing

        #pragma unroll
        for (int k16 = 0; k16 < 2; ++k16) {
            const uint32_t a_off = (uint32_t)(((k16 * 2 + (l >> 4)) ^ a_rs) * 16);
            const uint32_t b_off = (uint32_t)(((k16 * 2 + ((l >> 3) & 1)) ^ b_rs) * 16);
            uint32_t ahi[2][4], alo[2][4];
            #pragma unroll
            for (int mt = 0; mt < 2; ++mt) {
                const uint32_t aa = a_base0 + mt * (16 * 128) + a_off + soff;
                ldsm_x4(ahi[mt][0], ahi[mt][1], ahi[mt][2], ahi[mt][3], aa);
                ldsm_x4(alo[mt][0], alo[mt][1], alo[mt][2], alo[mt][3], aa ^ 64);
            }
            #pragma unroll
            for (int np = 0; np < 4; ++np) {
                const uint32_t ba = b_base0 + np * (16 * 64) + b_off + soff;
                uint32_t bh[4];
                ldsm_x4(bh[0], bh[1], bh[2], bh[3], ba);
                #pragma unroll
                for (int mt = 0; mt < 2; ++mt) {
                    #pragma unroll
                    for (int sub = 0; sub < 2; ++sub) {
                        float* a4 = acc[mt][np * 2 + sub];
                        mma16816(a4, ahi[mt], bh[sub * 2], bh[sub * 2 + 1]);
                        mma16816(a4, alo[mt], bh[sub * 2], bh[sub * 2 + 1]);
                    }
                }
            }
        }
    }

    // ---- epilogue ----
    const int row_base = mblk * 128 + wm * 32 + (l >> 2);
    const int col_base = nblk * 128 + wn * 64 + (l & 3) * 2;
    #pragma unroll
    for (int mt = 0; mt < 2; ++mt) {
        #pragma unroll
        for (int nt = 0; nt < 8; ++nt) {
            const int r0 = row_base + mt * 16;
            const int cc = col_base + nt * 8;
            float* o0 = out + (size_t)r0 * COUT + cc;
            float* o1 = out + (size_t)(r0 + 8) * COUT + cc;
            *reinterpret_cast<float2*>(o0) = make_float2(acc[mt][nt][0], acc[mt][nt][1]);
            *reinterpret_cast<float2*>(o1) = make_float2(acc[mt][nt][2], acc[mt][nt][3]);
        }
    }
}

// ---------------- launch ----------------
extern "C" void kernel_launch(void* const* d_in, const int* in_sizes, int n_in,
                              void* d_out, int out_size)
{
    const float* feats  = (const float*)d_in[0];
    const float* weight = (const float*)d_in[1];
    const float* alpha  = (const float*)d_in[2];
    float* out = (float*)d_out;

    cudaFuncSetAttribute(conv_mma_kernel,
                         cudaFuncAttributeMaxDynamicSharedMemorySize, SMEM_TOTAL);

    dim3 wgrid(K_TOTAL / 32, COUT / 32);   // (36, 8)
    wconv_kernel<<<wgrid, 256>>>(weight);
    asplit_kernel<<<(NPIX * CIN / 4 + 255) / 256, 256>>>(feats);
    dim3 grid(M_TOTAL / BM, COUT / BN);    // (256, 2)
    conv_mma_kernel<<<grid, NTHREADS, SMEM_TOTAL>>>(alpha, out);
}

// round 9
// speedup vs baseline: 2.8365x; 1.5435x over previous
#include <cuda_runtime.h>
#include <cuda_fp16.h>
#include <cstdint>

// ---------------- problem constants ----------------
#define CIN 128
#define COUT 256
#define NPIX (8 * 128 * 128)
#define M_TOTAL 32768                      // 8 * 64 * 64
#define K_TOTAL 1152                       // 9 * 128
#define FEATS_OUT_ELEMS ((size_t)M_TOTAL * COUT)
#define COORD_OUT_ELEMS ((size_t)M_TOTAL * 3)

// ---------------- GEMM config ----------------
#define BM 128
#define BN 128
#define BK 32                 // k per chunk
#define NCHUNK 36
#define NSTAGE 4
#define NTHREADS 256          // 8 warps: 4 m x 2 n, warp tile 32x64

// smem stage:
//   A: 128 rows x 64B (k 0..31 fp16), phys16B(chunk) = (chunk ^ ((row>>1)&3)) * 16
//   B: 128 rows x 64B, same swizzle
#define OFF_B 8192
#define STAGE_BYTES 16384
#define SMEM_TOTAL (NSTAGE * STAGE_BYTES)   // 65536; 2 CTAs/SM -> 128KB/SM

// ---------------- device scratch ----------------
__device__ __align__(16) __half g_Wh[COUT * K_TOTAL];            // [n][k] fp16
__device__ __align__(16) __half g_Ah[(size_t)NPIX * CIN];        // feats fp16

// ---------------- helpers ----------------
__device__ __forceinline__ uint32_t smem_u32(const void* p) {
    uint32_t a;
    asm("{ .reg .u64 t; cvta.to.shared.u64 t, %1; cvt.u32.u64 %0, t; }" : "=r"(a) : "l"(p));
    return a;
}
__device__ __forceinline__ void cp_async16(uint32_t dst, const void* src) {
    asm volatile("cp.async.cg.shared.global [%0], [%1], 16;" :: "r"(dst), "l"(src) : "memory");
}
__device__ __forceinline__ void cp_async16z(uint32_t dst, const void* src, uint32_t src_size) {
    asm volatile("cp.async.cg.shared.global [%0], [%1], 16, %2;"
                 :: "r"(dst), "l"(src), "r"(src_size) : "memory");
}
__device__ __forceinline__ void cp_commit() {
    asm volatile("cp.async.commit_group;" ::: "memory");
}
template <int N>
__device__ __forceinline__ void cp_wait() {
    asm volatile("cp.async.wait_group %0;" :: "n"(N) : "memory");
}
__device__ __forceinline__ void ldsm_x4(uint32_t& r0, uint32_t& r1, uint32_t& r2, uint32_t& r3,
                                        uint32_t addr) {
    asm volatile("ldmatrix.sync.aligned.m8n8.x4.shared.b16 {%0,%1,%2,%3}, [%4];"
                 : "=r"(r0), "=r"(r1), "=r"(r2), "=r"(r3) : "r"(addr));
}
__device__ __forceinline__ void mma16816(float* c, const uint32_t* a, uint32_t b0, uint32_t b1) {
    asm volatile("mma.sync.aligned.m16n8k16.row.col.f32.f16.f16.f32 "
                 "{%0,%1,%2,%3}, {%4,%5,%6,%7}, {%8,%9}, {%0,%1,%2,%3};"
                 : "+f"(c[0]), "+f"(c[1]), "+f"(c[2]), "+f"(c[3])
                 : "r"(a[0]), "r"(a[1]), "r"(a[2]), "r"(a[3]), "r"(b0), "r"(b1));
}

// ---------------- weight round + transpose (coalesced, tiled) ----------------
// weight[k][n] fp32 -> g_Wh [n][k] fp16
__global__ __launch_bounds__(256)
void wconv_kernel(const float* __restrict__ w) {
    __shared__ float tile[32][33];
    const int kt = blockIdx.x, nt = blockIdx.y;
    const int ty = threadIdx.x >> 5, tx = threadIdx.x & 31;
    #pragma unroll
    for (int j = 0; j < 4; ++j)
        tile[ty + j * 8][tx] = w[(size_t)(kt * 32 + ty + j * 8) * COUT + nt * 32 + tx];
    __syncthreads();
    #pragma unroll
    for (int j = 0; j < 4; ++j) {
        const int nr = nt * 32 + ty + j * 8;
        const int k  = kt * 32 + tx;
        g_Wh[(size_t)nr * K_TOTAL + k] = __float2half_rn(tile[tx][ty + j * 8]);
    }
}

// ---------------- feats round fp32 -> fp16 (streaming) ----------------
__global__ __launch_bounds__(256)
void around_kernel(const float* __restrict__ feats) {
    size_t i4 = (size_t)blockIdx.x * 256 + threadIdx.x;
    if (i4 < (size_t)NPIX * CIN / 4) {
        float4 v = reinterpret_cast<const float4*>(feats)[i4];
        __half2 h0 = __floats2half2_rn(v.x, v.y);
        __half2 h1 = __floats2half2_rn(v.z, v.w);
        reinterpret_cast<uint2*>(g_Ah)[i4] =
            make_uint2(*reinterpret_cast<uint32_t*>(&h0), *reinterpret_cast<uint32_t*>(&h1));
    }
}

// ---------------- main GEMM kernel ----------------
__global__ __launch_bounds__(NTHREADS, 2)
void conv_mma_kernel(const float* __restrict__ alpha,
                     float* __restrict__ out)
{
    extern __shared__ char smem[];
    const uint32_t sb = smem_u32(smem);
    const int tid = threadIdx.x;
    const int w = tid >> 5, l = tid & 31;
    const int mblk = blockIdx.x, nblk = blockIdx.y;
    const int wm = w & 3, wn = w >> 2;      // warp tile 32x64

    if (nblk == 0) {
        if (tid < 128) {
            int p = mblk * 128 + tid;
            float* row = out + FEATS_OUT_ELEMS + (size_t)p * 3;
            row[0] = (float)(p >> 12);
            row[1] = (float)((p & 4095) >> 6);
            row[2] = (float)(p & 63);
        }
        if (mblk == 0 && tid == 128)
            out[FEATS_OUT_ELEMS + COORD_OUT_ELEMS] = alpha[0];
    }

    // ---- loader geometry: thread t -> row t>>1, k-half h = t&1 (16 fp16 each)
    const int lrow = tid >> 1;
    const int lh   = tid & 1;
    const int p    = mblk * 128 + lrow;
    const int ab   = p >> 12;
    const int aoy  = ((p & 4095) >> 6) << 1;
    const int aox  = (p & 63) << 1;
    const int bgn  = nblk * 128 + lrow;

    // precomputed physical chunk offsets (swizzle: (chunk ^ ((row>>1)&3)) * 16)
    const int rsw = (lrow >> 1) & 3;
    const uint32_t c0 = ((2 * lh)     ^ rsw) * 16u;
    const uint32_t c1 = ((2 * lh + 1) ^ rsw) * 16u;

    auto issue_chunk = [&](int cc, int stg) {
        const int tap = cc >> 2, kc = (cc & 3) << 5;
        const int iy = aoy + tap / 3 - 1;
        const int ix = aox + tap % 3 - 1;
        const bool valid = ((unsigned)iy < 128u) && ((unsigned)ix < 128u);
        const uint32_t vs = valid ? 16u : 0u;
        const int cy = valid ? iy : 0, cx = valid ? ix : 0;
        const __half* asrc =
            g_Ah + ((size_t)(((ab << 7) + cy) << 7) + cx) * CIN + kc + lh * 16;
        const uint32_t stage = sb + (uint32_t)stg * STAGE_BYTES;
        const uint32_t arb = stage + lrow * 64;
        cp_async16z(arb + c0, asrc,     vs);
        cp_async16z(arb + c1, asrc + 8, vs);
        const __half* bsrc =
            g_Wh + (size_t)bgn * K_TOTAL + (size_t)tap * 128 + kc + lh * 16;
        const uint32_t brb = stage + OFF_B + lrow * 64;
        cp_async16(brb + c0, bsrc);
        cp_async16(brb + c1, bsrc + 8);
    };

    float acc[2][8][4];
    #pragma unroll
    for (int i = 0; i < 2; ++i)
        #pragma unroll
        for (int j = 0; j < 8; ++j)
            #pragma unroll
            for (int q = 0; q < 4; ++q) acc[i][j][q] = 0.f;

    // ---- ldsm addressing ----
    // A: arow = wm*32 + mt*16 + (l&15); chunk = k16*2 + (l>>4)
    const int arow_l = wm * 32 + (l & 15);
    const int a_rs   = (arow_l >> 1) & 3;          // invariant in mt (mt*16)
    const uint32_t a_base0 = sb + arow_l * 64;
    // B: brow = wn*64 + np*16 + ((l>>4)<<3) + (l&7); chunk = k16*2 + ((l>>3)&1)
    const int brow_l = wn * 64 + ((l >> 4) << 3) + (l & 7);
    const int b_rs   = (brow_l >> 1) & 3;          // invariant in np (np*16)
    const uint32_t b_base0 = sb + OFF_B + brow_l * 64;

    // ---- prologue: fill 3 stages ----
    issue_chunk(0, 0); cp_commit();
    issue_chunk(1, 1); cp_commit();
    issue_chunk(2, 2); cp_commit();

    #pragma unroll 1
    for (int c = 0; c < NCHUNK; ++c) {
        const uint32_t soff = (uint32_t)(c % NSTAGE) * STAGE_BYTES;

        cp_wait<2>();
        __syncthreads();           // all warps finished stage (c-1)%NSTAGE

        if (c + 3 < NCHUNK) issue_chunk(c + 3, (c + 3) % NSTAGE);
        cp_commit();               // unconditional: keeps group indices advancing

        #pragma unroll
        for (int k16 = 0; k16 < 2; ++k16) {
            const uint32_t a_off = (uint32_t)(((k16 * 2 + (l >> 4)) ^ a_rs) * 16);
            const uint32_t b_off = (uint32_t)(((k16 * 2 + ((l >> 3) & 1)) ^ b_rs) * 16);
            uint32_t af[2][4];
            #pragma unroll
            for (int mt = 0; mt < 2; ++mt) {
                const uint32_t aa = a_base0 + mt * (16 * 64) + a_off + soff;
                ldsm_x4(af[mt][0], af[mt][1], af[mt][2], af[mt][3], aa);
            }
            #pragma unroll
            for (int np = 0; np < 4; ++np) {
                const uint32_t ba = b_base0 + np * (16 * 64) + b_off + soff;
                uint32_t bh[4];
                ldsm_x4(bh[0], bh[1], bh[2], bh[3], ba);
                #pragma unroll
                for (int mt = 0; mt < 2; ++mt) {
                    #pragma unroll
                    for (int sub = 0; sub < 2; ++sub) {
                        mma16816(acc[mt][np * 2 + sub], af[mt],
                                 bh[sub * 2], bh[sub * 2 + 1]);
                    }
                }
            }
        }
    }

    // ---- epilogue ----
    const int row_base = mblk * 128 + wm * 32 + (l >> 2);
    const int col_base = nblk * 128 + wn * 64 + (l & 3) * 2;
    #pragma unroll
    for (int mt = 0; mt < 2; ++mt) {
        #pragma unroll
        for (int nt = 0; nt < 8; ++nt) {
            const int r0 = row_base + mt * 16;
            const int cc = col_base + nt * 8;
            float* o0 = out + (size_t)r0 * COUT + cc;
            float* o1 = out + (size_t)(r0 + 8) * COUT + cc;
            *reinterpret_cast<float2*>(o0) = make_float2(acc[mt][nt][0], acc[mt][nt][1]);
            *reinterpret_cast<float2*>(o1) = make_float2(acc[mt][nt][2], acc[mt][nt][3]);
        }
    }
}

// ---------------- launch ----------------
extern "C" void kernel_launch(void* const* d_in, const int* in_sizes, int n_in,
                              void* d_out, int out_size)
{
    const float* feats  = (const float*)d_in[0];
    const float* weight = (const float*)d_in[1];
    const float* alpha  = (const float*)d_in[2];
    float* out = (float*)d_out;

    cudaFuncSetAttribute(conv_mma_kernel,
                         cudaFuncAttributeMaxDynamicSharedMemorySize, SMEM_TOTAL);

    dim3 wgrid(K_TOTAL / 32, COUT / 32);   // (36, 8)
    wconv_kernel<<<wgrid, 256>>>(weight);
    around_kernel<<<(NPIX * CIN / 4 + 255) / 256, 256>>>(feats);
    dim3 grid(M_TOTAL / BM, COUT / BN);    // (256, 2)
    conv_mma_kernel<<<grid, NTHREADS, SMEM_TOTAL>>>(alpha, out);
}

// round 10
// speedup vs baseline: 3.1419x; 1.1077x over previous
#include <cuda_runtime.h>
#include <cuda_fp16.h>
#include <cstdint>

// ---------------- problem constants ----------------
#define CIN 128
#define COUT 256
#define NPIX (8 * 128 * 128)
#define M_TOTAL 32768                      // 8 * 64 * 64
#define K_TOTAL 1152                       // 9 * 128
#define FEATS_OUT_ELEMS ((size_t)M_TOTAL * COUT)
#define COORD_OUT_ELEMS ((size_t)M_TOTAL * 3)

// ---------------- GEMM config ----------------
#define BM 128
#define BN 128
#define BK 32
#define NCHUNK 36
#define NSTAGE 4
#define NTHREADS 512          // 16 warps: 4 m x 4 n, warp tile 32x32

// smem stage: A 128 rows x 64B, then B 128 rows x 64B
// phys16B(chunk) = (chunk ^ ((row>>1)&3)) * 16
#define OFF_B 8192
#define STAGE_BYTES 16384
#define SMEM_TOTAL (NSTAGE * STAGE_BYTES)   // 65536; 2 CTAs/SM

// ---------------- device scratch ----------------
__device__ __align__(16) __half g_Wh[COUT * K_TOTAL];            // [n][k] fp16
__device__ __align__(16) __half g_Ah[(size_t)NPIX * CIN];        // feats fp16

// ---------------- helpers ----------------
__device__ __forceinline__ uint32_t smem_u32(const void* p) {
    uint32_t a;
    asm("{ .reg .u64 t; cvta.to.shared.u64 t, %1; cvt.u32.u64 %0, t; }" : "=r"(a) : "l"(p));
    return a;
}
__device__ __forceinline__ void cp_async16(uint32_t dst, const void* src) {
    asm volatile("cp.async.cg.shared.global [%0], [%1], 16;" :: "r"(dst), "l"(src) : "memory");
}
__device__ __forceinline__ void cp_async16z(uint32_t dst, const void* src, uint32_t src_size) {
    asm volatile("cp.async.cg.shared.global [%0], [%1], 16, %2;"
                 :: "r"(dst), "l"(src), "r"(src_size) : "memory");
}
__device__ __forceinline__ void cp_commit() {
    asm volatile("cp.async.commit_group;" ::: "memory");
}
template <int N>
__device__ __forceinline__ void cp_wait() {
    asm volatile("cp.async.wait_group %0;" :: "n"(N) : "memory");
}
__device__ __forceinline__ void ldsm_x4(uint32_t& r0, uint32_t& r1, uint32_t& r2, uint32_t& r3,
                                        uint32_t addr) {
    asm volatile("ldmatrix.sync.aligned.m8n8.x4.shared.b16 {%0,%1,%2,%3}, [%4];"
                 : "=r"(r0), "=r"(r1), "=r"(r2), "=r"(r3) : "r"(addr));
}
__device__ __forceinline__ void mma16816(float* c, const uint32_t* a, uint32_t b0, uint32_t b1) {
    asm volatile("mma.sync.aligned.m16n8k16.row.col.f32.f16.f16.f32 "
                 "{%0,%1,%2,%3}, {%4,%5,%6,%7}, {%8,%9}, {%0,%1,%2,%3};"
                 : "+f"(c[0]), "+f"(c[1]), "+f"(c[2]), "+f"(c[3])
                 : "r"(a[0]), "r"(a[1]), "r"(a[2]), "r"(a[3]), "r"(b0), "r"(b1));
}

// ---------------- fused prep: feats fp32->fp16 stream + weight transpose ----------------
#define A4_TOTAL ((size_t)NPIX * CIN / 4)           // 4194304 float4
#define A4_BLOCKS 16384                              // A4_TOTAL / 256
__global__ __launch_bounds__(256)
void prep_kernel(const float* __restrict__ feats, const float* __restrict__ w) {
    __shared__ float tile[32][33];
    if (blockIdx.x < A4_BLOCKS) {
        size_t i4 = (size_t)blockIdx.x * 256 + threadIdx.x;
        float4 v = reinterpret_cast<const float4*>(feats)[i4];
        __half2 h0 = __floats2half2_rn(v.x, v.y);
        __half2 h1 = __floats2half2_rn(v.z, v.w);
        reinterpret_cast<uint2*>(g_Ah)[i4] =
            make_uint2(*reinterpret_cast<uint32_t*>(&h0), *reinterpret_cast<uint32_t*>(&h1));
    } else {
        const int bid = blockIdx.x - A4_BLOCKS;      // 0..287
        const int kt = bid % (K_TOTAL / 32);         // 36
        const int nt = bid / (K_TOTAL / 32);         // 8
        const int ty = threadIdx.x >> 5, tx = threadIdx.x & 31;
        #pragma unroll
        for (int j = 0; j < 4; ++j)
            tile[ty + j * 8][tx] = w[(size_t)(kt * 32 + ty + j * 8) * COUT + nt * 32 + tx];
        __syncthreads();
        #pragma unroll
        for (int j = 0; j < 4; ++j) {
            const int nr = nt * 32 + ty + j * 8;
            const int k  = kt * 32 + tx;
            g_Wh[(size_t)nr * K_TOTAL + k] = __float2half_rn(tile[tx][ty + j * 8]);
        }
    }
}

// ---------------- main GEMM kernel ----------------
__global__ __launch_bounds__(NTHREADS, 2)
void conv_mma_kernel(const float* __restrict__ alpha,
                     float* __restrict__ out)
{
    extern __shared__ char smem[];
    const uint32_t sb = smem_u32(smem);
    const int tid = threadIdx.x;
    const int w = tid >> 5, l = tid & 31;
    const int mblk = blockIdx.x, nblk = blockIdx.y;
    const int wm = w & 3, wn = w >> 2;      // 4m x 4n, warp tile 32x32

    if (nblk == 0) {
        if (tid < 128) {
            int p = mblk * 128 + tid;
            float* row = out + FEATS_OUT_ELEMS + (size_t)p * 3;
            row[0] = (float)(p >> 12);
            row[1] = (float)((p & 4095) >> 6);
            row[2] = (float)(p & 63);
        }
        if (mblk == 0 && tid == 128)
            out[FEATS_OUT_ELEMS + COORD_OUT_ELEMS] = alpha[0];
    }

    // ---- loader geometry: thread -> row tid>>2, 16B seg tid&3
    const int lrow = tid >> 2;
    const int lseg = tid & 3;
    const int p    = mblk * 128 + lrow;
    const int ab   = p >> 12;
    const int aoy  = ((p & 4095) >> 6) << 1;
    const int aox  = (p & 63) << 1;
    const int bgn  = nblk * 128 + lrow;
    const uint32_t csw = (uint32_t)((lseg ^ ((lrow >> 1) & 3)) * 16);

    auto issue_chunk = [&](int cc, int stg) {
        const int tap = cc >> 2, kc = (cc & 3) << 5;
        const int iy = aoy + tap / 3 - 1;
        const int ix = aox + tap % 3 - 1;
        const bool valid = ((unsigned)iy < 128u) && ((unsigned)ix < 128u);
        const uint32_t vs = valid ? 16u : 0u;
        const int cy = valid ? iy : 0, cx = valid ? ix : 0;
        const __half* asrc =
            g_Ah + ((size_t)(((ab << 7) + cy) << 7) + cx) * CIN + kc + lseg * 8;
        const uint32_t stage = sb + (uint32_t)stg * STAGE_BYTES;
        cp_async16z(stage + lrow * 64 + csw, asrc, vs);
        const __half* bsrc =
            g_Wh + (size_t)bgn * K_TOTAL + (size_t)tap * 128 + kc + lseg * 8;
        cp_async16(stage + OFF_B + lrow * 64 + csw, bsrc);
    };

    float acc[2][4][4];
    #pragma unroll
    for (int i = 0; i < 2; ++i)
        #pragma unroll
        for (int j = 0; j < 4; ++j)
            #pragma unroll
            for (int q = 0; q < 4; ++q) acc[i][j][q] = 0.f;

    // ---- ldsm addressing (frugal: 2 bases, offsets inline) ----
    const int arow_l = wm * 32 + (l & 15);
    const int a_rs   = (arow_l >> 1) & 3;
    const uint32_t a_base0 = sb + arow_l * 64;
    const int brow_l = wn * 32 + ((l >> 4) << 3) + (l & 7);
    const int b_rs   = (brow_l >> 1) & 3;
    const uint32_t b_base0 = sb + OFF_B + brow_l * 64;

    // ---- prologue: fill 3 stages ----
    issue_chunk(0, 0); cp_commit();
    issue_chunk(1, 1); cp_commit();
    issue_chunk(2, 2); cp_commit();

    #pragma unroll 1
    for (int c = 0; c < NCHUNK; ++c) {
        const uint32_t soff = (uint32_t)(c % NSTAGE) * STAGE_BYTES;

        cp_wait<2>();
        __syncthreads();

        if (c + 3 < NCHUNK) issue_chunk(c + 3, (c + 3) % NSTAGE);
        cp_commit();

        #pragma unroll
        for (int k16 = 0; k16 < 2; ++k16) {
            const uint32_t a_off = (uint32_t)(((k16 * 2 + (l >> 4)) ^ a_rs) * 16);
            const uint32_t b_off = (uint32_t)(((k16 * 2 + ((l >> 3) & 1)) ^ b_rs) * 16);
            uint32_t af[2][4], bh[4];
            ldsm_x4(af[0][0], af[0][1], af[0][2], af[0][3], a_base0 + a_off + soff);
            ldsm_x4(af[1][0], af[1][1], af[1][2], af[1][3],
                    a_base0 + 16 * 64 + a_off + soff);
            ldsm_x4(bh[0], bh[1], bh[2], bh[3], b_base0 + b_off + soff);
            #pragma unroll
            for (int mt = 0; mt < 2; ++mt) {
                #pragma unroll
                for (int sub = 0; sub < 2; ++sub) {
                    mma16816(acc[mt][sub], af[mt], bh[sub * 2], bh[sub * 2 + 1]);
                }
            }
            // second pair of n8 tiles: reuse af, load next B 16 rows
            ldsm_x4(bh[0], bh[1], bh[2], bh[3], b_base0 + 16 * 64 + b_off + soff);
            #pragma unroll
            for (int mt = 0; mt < 2; ++mt) {
                #pragma unroll
                for (int sub = 0; sub < 2; ++sub) {
                    mma16816(acc[mt][2 + sub], af[mt], bh[sub * 2], bh[sub * 2 + 1]);
                }
            }
        }
    }

    // ---- epilogue ----
    const int row_base = mblk * 128 + wm * 32 + (l >> 2);
    const int col_base = nblk * 128 + wn * 32 + (l & 3) * 2;
    #pragma unroll
    for (int mt = 0; mt < 2; ++mt) {
        #pragma unroll
        for (int nt = 0; nt < 4; ++nt) {
            const int r0 = row_base + mt * 16;
            const int cc = col_base + nt * 8;
            float* o0 = out + (size_t)r0 * COUT + cc;
            float* o1 = out + (size_t)(r0 + 8) * COUT + cc;
            *reinterpret_cast<float2*>(o0) = make_float2(acc[mt][nt][0], acc[mt][nt][1]);
            *reinterpret_cast<float2*>(o1) = make_float2(acc[mt][nt][2], acc[mt][nt][3]);
        }
    }
}

// ---------------- launch ----------------
extern "C" void kernel_launch(void* const* d_in, const int* in_sizes, int n_in,
                              void* d_out, int out_size)
{
    const float* feats  = (const float*)d_in[0];
    const float* weight = (const float*)d_in[1];
    const float* alpha  = (const float*)d_in[2];
    float* out = (float*)d_out;

    cudaFuncSetAttribute(conv_mma_kernel,
                         cudaFuncAttributeMaxDynamicSharedMemorySize, SMEM_TOTAL);

    prep_kernel<<<A4_BLOCKS + (K_TOTAL / 32) * (COUT / 32), 256>>>(feats, weight);
    dim3 grid(M_TOTAL / BM, COUT / BN);    // (256, 2)
    conv_mma_kernel<<<grid, NTHREADS, SMEM_TOTAL>>>(alpha, out);
}